// round 1
// baseline (speedup 1.0000x reference)
#include <cuda_runtime.h>
#include <cuda_bf16.h>
#include <math.h>

// Problem constants
#define Bz   8
#define Nn   4096
#define Cc   768
#define Hh   8
#define HD   96
#define M1   (Bz * Nn)          // 32768 tokens
#define BH   (Bz * Hh)          // 64
#define ROWS (BH * HD)          // 6144 rows per tensor (q or k)
#define ACHUNK 16               // split-K chunks for attention gram

// ---------------------------------------------------------------------------
// Device scratch (static allocations only; no cudaMalloc allowed)
// ---------------------------------------------------------------------------
__device__ float g_qkv[3ull * BH * HD * Nn];        // [t][b][h][d][n]  302 MB
__device__ float g_inv[2 * ROWS];                   // inverse L2 norms (q then k)
__device__ float g_attn_part[(size_t)ACHUNK * BH * HD * HD]; // split-K partials
__device__ float g_attn[(size_t)BH * HD * HD];      // softmaxed attention
__device__ float g_ctx[(size_t)BH * HD * Nn];       // attn @ v, [b][h][d][n]

// ---------------------------------------------------------------------------
// Kernel 1: QKV projection.  Y[m,j] = sum_k X[m,k] * Wqkv[j,k]
// Scatter epilogue writes directly into [t][b][h][d][n] layout.
// Tiled SGEMM: 128x128 block tile, K-tile 16, 8x8 per thread, 256 threads.
// ---------------------------------------------------------------------------
__global__ __launch_bounds__(256) void gemm_qkv_kernel(
    const float* __restrict__ X, const float* __restrict__ W) {
    __shared__ float As[16][132];
    __shared__ float Bs[16][132];
    const int K = Cc;
    int tid = threadIdx.x;
    int tx = tid & 15, ty = tid >> 4;
    int m0 = blockIdx.x * 128;
    int j0 = blockIdx.y * 128;
    const float* Ap = X + (size_t)m0 * K;
    const float* Bp = W + (size_t)j0 * K;

    float acc[8][8];
#pragma unroll
    for (int i = 0; i < 8; ++i)
#pragma unroll
        for (int j = 0; j < 8; ++j) acc[i][j] = 0.f;

    int lrow = tid >> 2;          // 0..63
    int lcol = (tid & 3) * 4;     // 0,4,8,12

    for (int kt = 0; kt < K; kt += 16) {
#pragma unroll
        for (int p = 0; p < 2; ++p) {
            int row = lrow + p * 64;
            float4 a = *(const float4*)(Ap + (size_t)row * K + kt + lcol);
            As[lcol + 0][row] = a.x; As[lcol + 1][row] = a.y;
            As[lcol + 2][row] = a.z; As[lcol + 3][row] = a.w;
            float4 b = *(const float4*)(Bp + (size_t)row * K + kt + lcol);
            Bs[lcol + 0][row] = b.x; Bs[lcol + 1][row] = b.y;
            Bs[lcol + 2][row] = b.z; Bs[lcol + 3][row] = b.w;
        }
        __syncthreads();
#pragma unroll
        for (int k = 0; k < 16; ++k) {
            float ra[8], rb[8];
            *(float4*)&ra[0] = *(const float4*)&As[k][tx * 4];
            *(float4*)&ra[4] = *(const float4*)&As[k][64 + tx * 4];
            *(float4*)&rb[0] = *(const float4*)&Bs[k][ty * 4];
            *(float4*)&rb[4] = *(const float4*)&Bs[k][64 + ty * 4];
#pragma unroll
            for (int i = 0; i < 8; ++i)
#pragma unroll
                for (int j = 0; j < 8; ++j)
                    acc[i][j] = fmaf(ra[i], rb[j], acc[i][j]);
        }
        __syncthreads();
    }

    // Scatter epilogue: m = b*4096+n ; j = t*768 + (h*96+d)
    // dest index = ((t*8+b)*768 + (h*96+d)) * 4096 + n   (contiguous over n)
    int b = m0 >> 12;
    int nbase = m0 & (Nn - 1);
#pragma unroll
    for (int jg = 0; jg < 2; ++jg) {
#pragma unroll
        for (int jl = 0; jl < 4; ++jl) {
            int jreg = jg * 4 + jl;
            int j = j0 + jg * 64 + ty * 4 + jl;
            int t = j / Cc;
            int r = j - t * Cc;               // h*96+d
            float* dst = g_qkv + ((size_t)(t * Bz + b) * Cc + r) * Nn + nbase;
            *(float4*)(dst + tx * 4) =
                make_float4(acc[0][jreg], acc[1][jreg], acc[2][jreg], acc[3][jreg]);
            *(float4*)(dst + 64 + tx * 4) =
                make_float4(acc[4][jreg], acc[5][jreg], acc[6][jreg], acc[7][jreg]);
        }
    }
}

// ---------------------------------------------------------------------------
// Kernel 2: inverse L2 norms over N for q and k rows (12288 rows total)
// ---------------------------------------------------------------------------
__global__ __launch_bounds__(256) void norms_kernel() {
    int idx = blockIdx.x;                       // 0..2*ROWS-1 (q rows then k rows)
    const float4* p4 = (const float4*)(g_qkv + (size_t)idx * Nn);
    int tid = threadIdx.x;
    float s = 0.f;
    for (int i = tid; i < Nn / 4; i += 256) {
        float4 v = p4[i];
        s = fmaf(v.x, v.x, s); s = fmaf(v.y, v.y, s);
        s = fmaf(v.z, v.z, s); s = fmaf(v.w, v.w, s);
    }
#pragma unroll
    for (int o = 16; o; o >>= 1) s += __shfl_xor_sync(0xffffffffu, s, o);
    __shared__ float red[8];
    if ((tid & 31) == 0) red[tid >> 5] = s;
    __syncthreads();
    if (tid == 0) {
        float t = 0.f;
#pragma unroll
        for (int w = 0; w < 8; ++w) t += red[w];
        g_inv[idx] = 1.0f / fmaxf(sqrtf(t), 1e-12f);
    }
}

// ---------------------------------------------------------------------------
// Kernel 3: split-K attention gram.  part[ch][bh][d][e] = sum_{n in chunk} q*k
// Block = (bh, chunk); 256 threads, 6x6 per thread over 96x96, inner tile n=32.
// ---------------------------------------------------------------------------
__global__ __launch_bounds__(256) void attn_part_kernel() {
    __shared__ float Qs[96][33];
    __shared__ float Ks[96][33];
    int bh = blockIdx.x;
    int ch = blockIdx.y;
    const int NPC = Nn / ACHUNK;                 // 256
    const float* qp = g_qkv + (size_t)bh * HD * Nn + ch * NPC;
    const float* kp = g_qkv + (size_t)ROWS * Nn + (size_t)bh * HD * Nn + ch * NPC;
    int tid = threadIdx.x;
    int tx = tid & 15, ty = tid >> 4;

    float acc[6][6];
#pragma unroll
    for (int i = 0; i < 6; ++i)
#pragma unroll
        for (int j = 0; j < 6; ++j) acc[i][j] = 0.f;

    for (int n0 = 0; n0 < NPC; n0 += 32) {
        int nl = tid & 31;
        for (int r = tid >> 5; r < 96; r += 8) {
            Qs[r][nl] = qp[(size_t)r * Nn + n0 + nl];
            Ks[r][nl] = kp[(size_t)r * Nn + n0 + nl];
        }
        __syncthreads();
#pragma unroll
        for (int e = 0; e < 32; ++e) {
            float rq[6], rk[6];
#pragma unroll
            for (int i = 0; i < 6; ++i) rq[i] = Qs[i * 16 + tx][e];
#pragma unroll
            for (int j = 0; j < 6; ++j) rk[j] = Ks[j * 16 + ty][e];
#pragma unroll
            for (int i = 0; i < 6; ++i)
#pragma unroll
                for (int j = 0; j < 6; ++j)
                    acc[i][j] = fmaf(rq[i], rk[j], acc[i][j]);
        }
        __syncthreads();
    }
    float* op = g_attn_part + ((size_t)ch * BH + bh) * (HD * HD);
#pragma unroll
    for (int i = 0; i < 6; ++i)
#pragma unroll
        for (int j = 0; j < 6; ++j)
            op[(i * 16 + tx) * HD + j * 16 + ty] = acc[i][j];
}

// ---------------------------------------------------------------------------
// Kernel 4: reduce split-K partials, scale by invq*invk*temperature, softmax
// over e (96).  One block per (bh,d) row, 128 threads.
// ---------------------------------------------------------------------------
__global__ __launch_bounds__(128) void softmax_kernel(const float* __restrict__ temperature) {
    int row = blockIdx.x;             // bh*96 + d
    int bh = row / HD;
    int h = bh & (Hh - 1);
    int tid = threadIdx.x;

    float v = -1e30f;
    if (tid < HD) {
        float s = 0.f;
#pragma unroll
        for (int c = 0; c < ACHUNK; ++c)
            s += g_attn_part[((size_t)c * ROWS + row) * HD + tid];
        s *= g_inv[row] * g_inv[ROWS + bh * HD + tid] * temperature[h];
        v = s;
    }
    __shared__ float red[4];
    float m = v;
#pragma unroll
    for (int o = 16; o; o >>= 1) m = fmaxf(m, __shfl_xor_sync(0xffffffffu, m, o));
    if ((tid & 31) == 0) red[tid >> 5] = m;
    __syncthreads();
    m = fmaxf(fmaxf(red[0], red[1]), fmaxf(red[2], red[3]));
    float e = (tid < HD) ? expf(v - m) : 0.f;
    __syncthreads();
    float s2 = e;
#pragma unroll
    for (int o = 16; o; o >>= 1) s2 += __shfl_xor_sync(0xffffffffu, s2, o);
    if ((tid & 31) == 0) red[tid >> 5] = s2;
    __syncthreads();
    float denom = red[0] + red[1] + red[2] + red[3];
    if (tid < HD) g_attn[(size_t)row * HD + tid] = e / denom;
}

// ---------------------------------------------------------------------------
// Kernel 5: ctx[bh][d][n] = sum_e attn[bh][d][e] * v[bh][e][n]
// Block = (bh, n-tile of 128).  attn tile cached in smem, v chunked over e.
// ---------------------------------------------------------------------------
__global__ __launch_bounds__(256) void ctx_kernel() {
    __shared__ float As[HD * HD];       // 36 KB
    __shared__ float Vs[16 * 128];      // 8 KB
    int bh = blockIdx.x;
    int n0 = blockIdx.y * 128;
    const float* vp = g_qkv + 2ull * ROWS * Nn + (size_t)bh * HD * Nn;
    int tid = threadIdx.x;
    int tx = tid & 31, ty = tid >> 5;   // ty: 0..7 (d group), tx: n lane

    for (int i = tid; i < HD * HD; i += 256)
        As[i] = g_attn[(size_t)bh * HD * HD + i];

    float acc[12][4];
#pragma unroll
    for (int id = 0; id < 12; ++id)
#pragma unroll
        for (int jn = 0; jn < 4; ++jn) acc[id][jn] = 0.f;

    for (int ec = 0; ec < HD / 16; ++ec) {
        __syncthreads();
        for (int i = tid; i < 16 * 128; i += 256)
            Vs[i] = vp[((size_t)ec * 16 + (i >> 7)) * Nn + n0 + (i & 127)];
        __syncthreads();
#pragma unroll
        for (int e = 0; e < 16; ++e) {
            float rv[4];
#pragma unroll
            for (int jn = 0; jn < 4; ++jn) rv[jn] = Vs[e * 128 + jn * 32 + tx];
#pragma unroll
            for (int id = 0; id < 12; ++id) {
                float a = As[(id * 8 + ty) * HD + ec * 16 + e];
#pragma unroll
                for (int jn = 0; jn < 4; ++jn)
                    acc[id][jn] = fmaf(a, rv[jn], acc[id][jn]);
            }
        }
    }
    float* cp = g_ctx + (size_t)bh * HD * Nn;
#pragma unroll
    for (int id = 0; id < 12; ++id)
#pragma unroll
        for (int jn = 0; jn < 4; ++jn)
            cp[(size_t)(id * 8 + ty) * Nn + n0 + jn * 32 + tx] = acc[id][jn];
}

// ---------------------------------------------------------------------------
// Kernel 6: output projection.  out[m,j] = sum_c ctx_gather[m,c]*Wp[j,c] + b[j]
// ctx is [b][h][d][n]; A-tile gather is coalesced along n.
// ---------------------------------------------------------------------------
__global__ __launch_bounds__(256) void gemm_proj_kernel(
    const float* __restrict__ Wp, const float* __restrict__ bias,
    float* __restrict__ out) {
    __shared__ float As[16][132];
    __shared__ float Bs[16][132];
    const int K = Cc;
    int tid = threadIdx.x;
    int tx = tid & 15, ty = tid >> 4;
    int m0 = blockIdx.x * 128;
    int j0 = blockIdx.y * 128;
    int b = m0 >> 12;
    int nbase = m0 & (Nn - 1);
    const float* Bp = Wp + (size_t)j0 * K;

    float acc[8][8];
#pragma unroll
    for (int i = 0; i < 8; ++i)
#pragma unroll
        for (int j = 0; j < 8; ++j) acc[i][j] = 0.f;

    int lrow = tid >> 2;
    int lcol = (tid & 3) * 4;
    int ml = tid & 127;
    int k0 = tid >> 7;                  // 0 or 1

    for (int kt = 0; kt < K; kt += 16) {
        // A gather: As[k][m] = ctx[(b*768 + kt+k)*4096 + nbase + m]
#pragma unroll
        for (int kk = 0; kk < 8; ++kk) {
            int k = k0 + kk * 2;
            As[k][ml] = g_ctx[((size_t)b * Cc + kt + k) * Nn + nbase + ml];
        }
#pragma unroll
        for (int p = 0; p < 2; ++p) {
            int row = lrow + p * 64;
            float4 bv = *(const float4*)(Bp + (size_t)row * K + kt + lcol);
            Bs[lcol + 0][row] = bv.x; Bs[lcol + 1][row] = bv.y;
            Bs[lcol + 2][row] = bv.z; Bs[lcol + 3][row] = bv.w;
        }
        __syncthreads();
#pragma unroll
        for (int k = 0; k < 16; ++k) {
            float ra[8], rb[8];
            *(float4*)&ra[0] = *(const float4*)&As[k][tx * 4];
            *(float4*)&ra[4] = *(const float4*)&As[k][64 + tx * 4];
            *(float4*)&rb[0] = *(const float4*)&Bs[k][ty * 4];
            *(float4*)&rb[4] = *(const float4*)&Bs[k][64 + ty * 4];
#pragma unroll
            for (int i = 0; i < 8; ++i)
#pragma unroll
                for (int j = 0; j < 8; ++j)
                    acc[i][j] = fmaf(ra[i], rb[j], acc[i][j]);
        }
        __syncthreads();
    }

    // bias + store (float4 along j)
    float bj[8];
#pragma unroll
    for (int jg = 0; jg < 2; ++jg)
#pragma unroll
        for (int jl = 0; jl < 4; ++jl)
            bj[jg * 4 + jl] = bias[j0 + jg * 64 + ty * 4 + jl];

#pragma unroll
    for (int ig = 0; ig < 2; ++ig) {
#pragma unroll
        for (int il = 0; il < 4; ++il) {
            int i = ig * 4 + il;
            int m = m0 + ig * 64 + tx * 4 + il;
            *(float4*)(out + (size_t)m * Cc + j0 + ty * 4) =
                make_float4(acc[i][0] + bj[0], acc[i][1] + bj[1],
                            acc[i][2] + bj[2], acc[i][3] + bj[3]);
            *(float4*)(out + (size_t)m * Cc + j0 + 64 + ty * 4) =
                make_float4(acc[i][4] + bj[4], acc[i][5] + bj[5],
                            acc[i][6] + bj[6], acc[i][7] + bj[7]);
        }
    }
}

// ---------------------------------------------------------------------------
// Launcher
// ---------------------------------------------------------------------------
extern "C" void kernel_launch(void* const* d_in, const int* in_sizes, int n_in,
                              void* d_out, int out_size) {
    const float* x      = (const float*)d_in[0];
    const float* w_qkv  = (const float*)d_in[1];
    const float* temp   = (const float*)d_in[2];
    const float* w_proj = (const float*)d_in[3];
    const float* b_proj = (const float*)d_in[4];
    float* out = (float*)d_out;

    gemm_qkv_kernel<<<dim3(M1 / 128, (3 * Cc) / 128), 256>>>(x, w_qkv);
    norms_kernel<<<2 * ROWS, 256>>>();
    attn_part_kernel<<<dim3(BH, ACHUNK), 256>>>();
    softmax_kernel<<<ROWS, 128>>>(temp);
    ctx_kernel<<<dim3(BH, Nn / 128), 256>>>();
    gemm_proj_kernel<<<dim3(M1 / 128, Cc / 128), 256>>>(w_proj, b_proj, out);
}

// round 3
// speedup vs baseline: 1.5518x; 1.5518x over previous
#include <cuda_runtime.h>
#include <cuda_bf16.h>
#include <math.h>
#include <cstdint>

// Problem constants
#define Bz   8
#define Nn   4096
#define Cc   768
#define Hh   8
#define HD   96
#define M1   (Bz * Nn)          // 32768 tokens
#define BH   (Bz * Hh)          // 64
#define ROWS (BH * HD)          // 6144 rows per tensor (q or k)
#define ACHUNK 16               // split-K chunks for attention gram

// ---------------------------------------------------------------------------
// Device scratch
// ---------------------------------------------------------------------------
__device__ float g_qkv[3ull * BH * HD * Nn];                 // [t][b][h][d][n]
__device__ float g_inv[2 * ROWS];
__device__ float g_attn_part[(size_t)ACHUNK * BH * HD * HD];
__device__ float g_attn[(size_t)BH * HD * HD];
__device__ __nv_bfloat16 g_ctx_hi[(size_t)M1 * Cc];          // ctx [m][c] hi
__device__ __nv_bfloat16 g_ctx_lo[(size_t)M1 * Cc];          // ctx [m][c] lo

// ---------------------------------------------------------------------------
// MMA helpers (baseline PTX, no 'a'-target features)
// ---------------------------------------------------------------------------
#define LDSM4(R, A)                                                           \
    asm volatile("ldmatrix.sync.aligned.m8n8.x4.shared.b16 {%0,%1,%2,%3}, [%4];" \
        : "=r"((R)[0]), "=r"((R)[1]), "=r"((R)[2]), "=r"((R)[3]) : "r"(A))

#define MMA16816(C, A, B0, B1)                                                \
    asm volatile("mma.sync.aligned.m16n8k16.row.col.f32.bf16.bf16.f32 "       \
        "{%0,%1,%2,%3}, {%4,%5,%6,%7}, {%8,%9}, {%0,%1,%2,%3};"               \
        : "+f"((C)[0]), "+f"((C)[1]), "+f"((C)[2]), "+f"((C)[3])              \
        : "r"((A)[0]), "r"((A)[1]), "r"((A)[2]), "r"((A)[3]), "r"(B0), "r"(B1))

__device__ __forceinline__ void split2(float x, float y, uint32_t& hi, uint32_t& lo) {
    __nv_bfloat16 hx = __float2bfloat16(x), hy = __float2bfloat16(y);
    __nv_bfloat16 lx = __float2bfloat16(x - __bfloat162float(hx));
    __nv_bfloat16 ly = __float2bfloat16(y - __bfloat162float(hy));
    hi = (uint32_t)__bfloat16_as_ushort(hx) | ((uint32_t)__bfloat16_as_ushort(hy) << 16);
    lo = (uint32_t)__bfloat16_as_ushort(lx) | ((uint32_t)__bfloat16_as_ushort(ly) << 16);
}

// smem tile geometry: 128 rows x 32 halves, padded to 40 halves (80B row)
#define TPAD 40
#define TILE_B (128 * TPAD * 2)       // 10240 bytes per tile

// ---------------------------------------------------------------------------
// Kernel 1: QKV GEMM via mma.sync 3xBF16.  Y = X @ Wqkv^T, scatter epilogue.
// Grid (18 j-tiles, 256 m-tiles), 256 threads = 8 warps (4M x 2N), warp 32x64.
// ---------------------------------------------------------------------------
__global__ __launch_bounds__(256) void qkv_mma_kernel(
    const float* __restrict__ X, const float* __restrict__ W) {
    __shared__ __align__(1024) char smem_raw[4 * TILE_B];
    __nv_bfloat16* sAhi = (__nv_bfloat16*)smem_raw;
    __nv_bfloat16* sAlo = (__nv_bfloat16*)(smem_raw + TILE_B);
    __nv_bfloat16* sBhi = (__nv_bfloat16*)(smem_raw + 2 * TILE_B);
    __nv_bfloat16* sBlo = (__nv_bfloat16*)(smem_raw + 3 * TILE_B);
    float* stage = (float*)smem_raw;    // epilogue staging, 64x132 floats

    const int tid = threadIdx.x, l = tid & 31, w = tid >> 5;
    const int wm = w & 3, wn = w >> 2;
    const int j0 = blockIdx.x * 128, m0 = blockIdx.y * 128;
    const float* Ap = X + (size_t)m0 * Cc;
    const float* Bp = W + (size_t)j0 * Cc;

    const uint32_t sAhiB = (uint32_t)__cvta_generic_to_shared(sAhi);
    const uint32_t sAloB = (uint32_t)__cvta_generic_to_shared(sAlo);
    const uint32_t sBhiB = (uint32_t)__cvta_generic_to_shared(sBhi);
    const uint32_t sBloB = (uint32_t)__cvta_generic_to_shared(sBlo);
    const uint32_t aoff = (uint32_t)(((wm * 32 + (l & 15)) * TPAD + (l >> 4) * 8) * 2);
    const uint32_t boff = (uint32_t)(((wn * 64 + (l & 15)) * TPAD + (l >> 4) * 8) * 2);

    float acc[2][8][4];
#pragma unroll
    for (int mt = 0; mt < 2; ++mt)
#pragma unroll
        for (int ni = 0; ni < 8; ++ni)
#pragma unroll
            for (int q = 0; q < 4; ++q) acc[mt][ni][q] = 0.f;

    const int pr = tid >> 3, pc = tid & 7;   // producer: rows pr+32i, float4 col pc
    float4 pa[4], pb[4];
#pragma unroll
    for (int i = 0; i < 4; ++i) {
        pa[i] = *(const float4*)(Ap + (size_t)(pr + i * 32) * Cc + pc * 4);
        pb[i] = *(const float4*)(Bp + (size_t)(pr + i * 32) * Cc + pc * 4);
    }

    for (int kt = 0; kt < Cc; kt += 32) {
        // STS: split fp32 -> bf16 hi/lo
#pragma unroll
        for (int i = 0; i < 4; ++i) {
            int r = pr + i * 32;
            uint2 h, lo;
            split2(pa[i].x, pa[i].y, h.x, lo.x); split2(pa[i].z, pa[i].w, h.y, lo.y);
            *(uint2*)&sAhi[r * TPAD + pc * 4] = h;
            *(uint2*)&sAlo[r * TPAD + pc * 4] = lo;
            split2(pb[i].x, pb[i].y, h.x, lo.x); split2(pb[i].z, pb[i].w, h.y, lo.y);
            *(uint2*)&sBhi[r * TPAD + pc * 4] = h;
            *(uint2*)&sBlo[r * TPAD + pc * 4] = lo;
        }
        __syncthreads();
        if (kt + 32 < Cc) {
#pragma unroll
            for (int i = 0; i < 4; ++i) {
                pa[i] = *(const float4*)(Ap + (size_t)(pr + i * 32) * Cc + kt + 32 + pc * 4);
                pb[i] = *(const float4*)(Bp + (size_t)(pr + i * 32) * Cc + kt + 32 + pc * 4);
            }
        }
#pragma unroll
        for (int kk = 0; kk < 32; kk += 16) {
            uint32_t ah[2][4], al[2][4], bh[4][4], bl[4][4];
#pragma unroll
            for (int mt = 0; mt < 2; ++mt) {
                uint32_t o = aoff + (uint32_t)((mt * 16 * TPAD + kk) * 2);
                LDSM4(ah[mt], sAhiB + o);
                LDSM4(al[mt], sAloB + o);
            }
#pragma unroll
            for (int nt = 0; nt < 4; ++nt) {
                uint32_t o = boff + (uint32_t)((nt * 16 * TPAD + kk) * 2);
                LDSM4(bh[nt], sBhiB + o);
                LDSM4(bl[nt], sBloB + o);
            }
#pragma unroll
            for (int mt = 0; mt < 2; ++mt)
#pragma unroll
                for (int nt = 0; nt < 4; ++nt)
#pragma unroll
                    for (int h = 0; h < 2; ++h) {
                        float* c = acc[mt][nt * 2 + h];
                        MMA16816(c, ah[mt], bh[nt][h], bh[nt][h + 2]);
                        MMA16816(c, ah[mt], bl[nt][h], bl[nt][h + 2]);
                        MMA16816(c, al[mt], bh[nt][h], bh[nt][h + 2]);
                    }
        }
        __syncthreads();
    }

    // Epilogue: stage 64 j-cols at a time as stage[j][m], coalesced scatter
    const int b = m0 >> 12, nb = m0 & (Nn - 1);
#pragma unroll
    for (int c = 0; c < 2; ++c) {
        if (wn == c) {
#pragma unroll
            for (int mt = 0; mt < 2; ++mt)
#pragma unroll
                for (int ni = 0; ni < 8; ++ni) {
                    int nt = ni >> 1, h = ni & 1;
                    int jl = nt * 16 + h * 8 + (l & 3) * 2;
                    int ml = wm * 32 + mt * 16 + (l >> 2);
                    const float* d = acc[mt][ni];
                    stage[jl * 132 + ml] = d[0];
                    stage[(jl + 1) * 132 + ml] = d[1];
                    stage[jl * 132 + ml + 8] = d[2];
                    stage[(jl + 1) * 132 + ml + 8] = d[3];
                }
        }
        __syncthreads();
        {
            int jl = tid >> 2, f4 = tid & 3;
            int j = j0 + c * 64 + jl;
            int t = j / Cc, r = j - t * Cc;
            float* dst = g_qkv + ((size_t)(t * Bz + b) * Cc + r) * Nn + nb;
#pragma unroll
            for (int i = 0; i < 8; ++i) {
                int idx = f4 + i * 4;
                *(float4*)(dst + idx * 4) = *(float4*)(stage + jl * 132 + idx * 4);
            }
        }
        __syncthreads();
    }
}

// ---------------------------------------------------------------------------
// Kernel 2: inverse L2 norms over N for q and k rows
// ---------------------------------------------------------------------------
__global__ __launch_bounds__(256) void norms_kernel() {
    int idx = blockIdx.x;
    const float4* p4 = (const float4*)(g_qkv + (size_t)idx * Nn);
    int tid = threadIdx.x;
    float s = 0.f;
    for (int i = tid; i < Nn / 4; i += 256) {
        float4 v = p4[i];
        s = fmaf(v.x, v.x, s); s = fmaf(v.y, v.y, s);
        s = fmaf(v.z, v.z, s); s = fmaf(v.w, v.w, s);
    }
#pragma unroll
    for (int o = 16; o; o >>= 1) s += __shfl_xor_sync(0xffffffffu, s, o);
    __shared__ float red[8];
    if ((tid & 31) == 0) red[tid >> 5] = s;
    __syncthreads();
    if (tid == 0) {
        float t = 0.f;
#pragma unroll
        for (int w = 0; w < 8; ++w) t += red[w];
        g_inv[idx] = 1.0f / fmaxf(sqrtf(t), 1e-12f);
    }
}

// ---------------------------------------------------------------------------
// Kernel 3: split-K attention gram (fp32)
// ---------------------------------------------------------------------------
__global__ __launch_bounds__(256) void attn_part_kernel() {
    __shared__ float Qs[96][33];
    __shared__ float Ks[96][33];
    int bh = blockIdx.x;
    int ch = blockIdx.y;
    const int NPC = Nn / ACHUNK;
    const float* qp = g_qkv + (size_t)bh * HD * Nn + ch * NPC;
    const float* kp = g_qkv + (size_t)ROWS * Nn + (size_t)bh * HD * Nn + ch * NPC;
    int tid = threadIdx.x;
    int tx = tid & 15, ty = tid >> 4;

    float acc[6][6];
#pragma unroll
    for (int i = 0; i < 6; ++i)
#pragma unroll
        for (int j = 0; j < 6; ++j) acc[i][j] = 0.f;

    for (int n0 = 0; n0 < NPC; n0 += 32) {
        int nl = tid & 31;
        for (int r = tid >> 5; r < 96; r += 8) {
            Qs[r][nl] = qp[(size_t)r * Nn + n0 + nl];
            Ks[r][nl] = kp[(size_t)r * Nn + n0 + nl];
        }
        __syncthreads();
#pragma unroll
        for (int e = 0; e < 32; ++e) {
            float rq[6], rk[6];
#pragma unroll
            for (int i = 0; i < 6; ++i) rq[i] = Qs[i * 16 + tx][e];
#pragma unroll
            for (int j = 0; j < 6; ++j) rk[j] = Ks[j * 16 + ty][e];
#pragma unroll
            for (int i = 0; i < 6; ++i)
#pragma unroll
                for (int j = 0; j < 6; ++j)
                    acc[i][j] = fmaf(rq[i], rk[j], acc[i][j]);
        }
        __syncthreads();
    }
    float* op = g_attn_part + ((size_t)ch * BH + bh) * (HD * HD);
#pragma unroll
    for (int i = 0; i < 6; ++i)
#pragma unroll
        for (int j = 0; j < 6; ++j)
            op[(i * 16 + tx) * HD + j * 16 + ty] = acc[i][j];
}

// ---------------------------------------------------------------------------
// Kernel 4: reduce + scale + softmax
// ---------------------------------------------------------------------------
__global__ __launch_bounds__(128) void softmax_kernel(const float* __restrict__ temperature) {
    int row = blockIdx.x;
    int bh = row / HD;
    int h = bh & (Hh - 1);
    int tid = threadIdx.x;

    float v = -1e30f;
    if (tid < HD) {
        float s = 0.f;
#pragma unroll
        for (int c = 0; c < ACHUNK; ++c)
            s += g_attn_part[((size_t)c * ROWS + row) * HD + tid];
        s *= g_inv[row] * g_inv[ROWS + bh * HD + tid] * temperature[h];
        v = s;
    }
    __shared__ float red[4];
    float m = v;
#pragma unroll
    for (int o = 16; o; o >>= 1) m = fmaxf(m, __shfl_xor_sync(0xffffffffu, m, o));
    if ((tid & 31) == 0) red[tid >> 5] = m;
    __syncthreads();
    m = fmaxf(fmaxf(red[0], red[1]), fmaxf(red[2], red[3]));
    float e = (tid < HD) ? expf(v - m) : 0.f;
    __syncthreads();
    float s2 = e;
#pragma unroll
    for (int o = 16; o; o >>= 1) s2 += __shfl_xor_sync(0xffffffffu, s2, o);
    if ((tid & 31) == 0) red[tid >> 5] = s2;
    __syncthreads();
    float denom = red[0] + red[1] + red[2] + red[3];
    if (tid < HD) g_attn[(size_t)row * HD + tid] = e / denom;
}

// ---------------------------------------------------------------------------
// Kernel 5: ctx = attn @ v, emits bf16 hi/lo in [m][c] layout (proj A operand)
// ---------------------------------------------------------------------------
__global__ __launch_bounds__(256) void ctx_kernel() {
    __shared__ float At[HD * HD];      // transposed attn: At[e*96 + d]
    __shared__ float Vs[16 * 128];
    int bh = blockIdx.x, n0 = blockIdx.y * 128;
    int tid = threadIdx.x, w = tid >> 5, lane = tid & 31;
    const float* vp = g_qkv + 2ull * ROWS * Nn + (size_t)bh * HD * Nn;

    for (int i = tid; i < HD * HD; i += 256) {
        int d = i / HD, e = i % HD;
        At[e * HD + d] = g_attn[(size_t)bh * HD * HD + i];
    }

    float acc[3][16];
#pragma unroll
    for (int dg = 0; dg < 3; ++dg)
#pragma unroll
        for (int nn = 0; nn < 16; ++nn) acc[dg][nn] = 0.f;

    for (int ec = 0; ec < HD / 16; ++ec) {
        __syncthreads();
        for (int i = tid; i < 16 * 128; i += 256)
            Vs[i] = vp[(size_t)(ec * 16 + (i >> 7)) * Nn + n0 + (i & 127)];
        __syncthreads();
#pragma unroll
        for (int e = 0; e < 16; ++e) {
            float a0 = At[(ec * 16 + e) * HD + lane];
            float a1 = At[(ec * 16 + e) * HD + 32 + lane];
            float a2 = At[(ec * 16 + e) * HD + 64 + lane];
#pragma unroll
            for (int nn = 0; nn < 16; ++nn) {
                float vv = Vs[e * 128 + w * 16 + nn];
                acc[0][nn] = fmaf(a0, vv, acc[0][nn]);
                acc[1][nn] = fmaf(a1, vv, acc[1][nn]);
                acc[2][nn] = fmaf(a2, vv, acc[2][nn]);
            }
        }
    }
    int b = bh >> 3, h = bh & 7;
#pragma unroll
    for (int dg = 0; dg < 3; ++dg)
#pragma unroll
        for (int nn = 0; nn < 16; ++nn) {
            float v = acc[dg][nn];
            __nv_bfloat16 hi = __float2bfloat16(v);
            __nv_bfloat16 lo = __float2bfloat16(v - __bfloat162float(hi));
            size_t base = ((size_t)(b * Nn + n0 + w * 16 + nn)) * Cc + h * HD + dg * 32 + lane;
            g_ctx_hi[base] = hi;
            g_ctx_lo[base] = lo;
        }
}

// ---------------------------------------------------------------------------
// Kernel 6: proj GEMM via mma.sync 3xBF16.  out = ctx @ Wp^T + bias.
// ---------------------------------------------------------------------------
__global__ __launch_bounds__(256) void proj_mma_kernel(
    const float* __restrict__ Wp, const float* __restrict__ bias,
    float* __restrict__ out) {
    __shared__ __align__(1024) char smem_raw[4 * TILE_B];
    __nv_bfloat16* sAhi = (__nv_bfloat16*)smem_raw;
    __nv_bfloat16* sAlo = (__nv_bfloat16*)(smem_raw + TILE_B);
    __nv_bfloat16* sBhi = (__nv_bfloat16*)(smem_raw + 2 * TILE_B);
    __nv_bfloat16* sBlo = (__nv_bfloat16*)(smem_raw + 3 * TILE_B);
    float* stage = (float*)smem_raw;    // epilogue staging, 128x68 floats

    const int tid = threadIdx.x, l = tid & 31, w = tid >> 5;
    const int wm = w & 3, wn = w >> 2;
    const int j0 = blockIdx.x * 128, m0 = blockIdx.y * 128;
    const float* Bp = Wp + (size_t)j0 * Cc;

    const uint32_t sAhiB = (uint32_t)__cvta_generic_to_shared(sAhi);
    const uint32_t sAloB = (uint32_t)__cvta_generic_to_shared(sAlo);
    const uint32_t sBhiB = (uint32_t)__cvta_generic_to_shared(sBhi);
    const uint32_t sBloB = (uint32_t)__cvta_generic_to_shared(sBlo);
    const uint32_t aoff = (uint32_t)(((wm * 32 + (l & 15)) * TPAD + (l >> 4) * 8) * 2);
    const uint32_t boff = (uint32_t)(((wn * 64 + (l & 15)) * TPAD + (l >> 4) * 8) * 2);

    float acc[2][8][4];
#pragma unroll
    for (int mt = 0; mt < 2; ++mt)
#pragma unroll
        for (int ni = 0; ni < 8; ++ni)
#pragma unroll
            for (int q = 0; q < 4; ++q) acc[mt][ni][q] = 0.f;

    // A producer: bf16 hi/lo direct loads (uint4 = 8 halves)
    const int ar = tid >> 2, aq = tid & 3;
    // B producer: fp32 W rows
    const int pr = tid >> 3, pc = tid & 7;

    uint4 pah[2], pal[2];
    float4 pb[4];
#pragma unroll
    for (int i = 0; i < 2; ++i) {
        size_t go = (size_t)(m0 + ar + i * 64) * Cc;
        pah[i] = ((const uint4*)(g_ctx_hi + go))[aq];
        pal[i] = ((const uint4*)(g_ctx_lo + go))[aq];
    }
#pragma unroll
    for (int i = 0; i < 4; ++i)
        pb[i] = *(const float4*)(Bp + (size_t)(pr + i * 32) * Cc + pc * 4);

    for (int kt = 0; kt < Cc; kt += 32) {
#pragma unroll
        for (int i = 0; i < 2; ++i) {
            int r = ar + i * 64;
            *(uint4*)&sAhi[r * TPAD + aq * 8] = pah[i];
            *(uint4*)&sAlo[r * TPAD + aq * 8] = pal[i];
        }
#pragma unroll
        for (int i = 0; i < 4; ++i) {
            int r = pr + i * 32;
            uint2 h, lo;
            split2(pb[i].x, pb[i].y, h.x, lo.x); split2(pb[i].z, pb[i].w, h.y, lo.y);
            *(uint2*)&sBhi[r * TPAD + pc * 4] = h;
            *(uint2*)&sBlo[r * TPAD + pc * 4] = lo;
        }
        __syncthreads();
        if (kt + 32 < Cc) {
#pragma unroll
            for (int i = 0; i < 2; ++i) {
                size_t go = (size_t)(m0 + ar + i * 64) * Cc + kt + 32;
                pah[i] = ((const uint4*)(g_ctx_hi + go))[aq];
                pal[i] = ((const uint4*)(g_ctx_lo + go))[aq];
            }
#pragma unroll
            for (int i = 0; i < 4; ++i)
                pb[i] = *(const float4*)(Bp + (size_t)(pr + i * 32) * Cc + kt + 32 + pc * 4);
        }
#pragma unroll
        for (int kk = 0; kk < 32; kk += 16) {
            uint32_t ah[2][4], al[2][4], bh[4][4], bl[4][4];
#pragma unroll
            for (int mt = 0; mt < 2; ++mt) {
                uint32_t o = aoff + (uint32_t)((mt * 16 * TPAD + kk) * 2);
                LDSM4(ah[mt], sAhiB + o);
                LDSM4(al[mt], sAloB + o);
            }
#pragma unroll
            for (int nt = 0; nt < 4; ++nt) {
                uint32_t o = boff + (uint32_t)((nt * 16 * TPAD + kk) * 2);
                LDSM4(bh[nt], sBhiB + o);
                LDSM4(bl[nt], sBloB + o);
            }
#pragma unroll
            for (int mt = 0; mt < 2; ++mt)
#pragma unroll
                for (int nt = 0; nt < 4; ++nt)
#pragma unroll
                    for (int h = 0; h < 2; ++h) {
                        float* c = acc[mt][nt * 2 + h];
                        MMA16816(c, ah[mt], bh[nt][h], bh[nt][h + 2]);
                        MMA16816(c, ah[mt], bl[nt][h], bl[nt][h + 2]);
                        MMA16816(c, al[mt], bh[nt][h], bh[nt][h + 2]);
                    }
        }
        __syncthreads();
    }

    // Epilogue: stage[m][j] per 64-col chunk, coalesced row-major store + bias
#pragma unroll
    for (int c = 0; c < 2; ++c) {
        if (wn == c) {
#pragma unroll
            for (int mt = 0; mt < 2; ++mt)
#pragma unroll
                for (int ni = 0; ni < 8; ++ni) {
                    int nt = ni >> 1, h = ni & 1;
                    int jl = nt * 16 + h * 8 + (l & 3) * 2;
                    int ml = wm * 32 + mt * 16 + (l >> 2);
                    const float* d = acc[mt][ni];
                    stage[ml * 68 + jl] = d[0];
                    stage[ml * 68 + jl + 1] = d[1];
                    stage[(ml + 8) * 68 + jl] = d[2];
                    stage[(ml + 8) * 68 + jl + 1] = d[3];
                }
        }
        __syncthreads();
        {
            int ml = tid >> 1, half = tid & 1;
            int jb = j0 + c * 64 + half * 32;
#pragma unroll
            for (int i = 0; i < 8; ++i) {
                float4 v = *(float4*)(stage + ml * 68 + half * 32 + i * 4);
                float4 bb = *(const float4*)(bias + jb + i * 4);
                v.x += bb.x; v.y += bb.y; v.z += bb.z; v.w += bb.w;
                *(float4*)(out + (size_t)(m0 + ml) * Cc + jb + i * 4) = v;
            }
        }
        __syncthreads();
    }
}

// ---------------------------------------------------------------------------
// Launcher
// ---------------------------------------------------------------------------
extern "C" void kernel_launch(void* const* d_in, const int* in_sizes, int n_in,
                              void* d_out, int out_size) {
    const float* x      = (const float*)d_in[0];
    const float* w_qkv  = (const float*)d_in[1];
    const float* temp   = (const float*)d_in[2];
    const float* w_proj = (const float*)d_in[3];
    const float* b_proj = (const float*)d_in[4];
    float* out = (float*)d_out;

    qkv_mma_kernel<<<dim3(3 * Cc / 128, M1 / 128), 256>>>(x, w_qkv);
    norms_kernel<<<2 * ROWS, 256>>>();
    attn_part_kernel<<<dim3(BH, ACHUNK), 256>>>();
    softmax_kernel<<<ROWS, 128>>>(temp);
    ctx_kernel<<<dim3(BH, Nn / 128), 256>>>();
    proj_mma_kernel<<<dim3(Cc / 128, M1 / 128), 256>>>(w_proj, b_proj, out);
}

// round 4
// speedup vs baseline: 1.7713x; 1.1415x over previous
#include <cuda_runtime.h>
#include <cuda_bf16.h>
#include <math.h>
#include <cstdint>

// Problem constants
#define Bz   8
#define Nn   4096
#define Cc   768
#define Hh   8
#define HD   96
#define M1   (Bz * Nn)          // 32768 tokens
#define BH   (Bz * Hh)          // 64
#define ROWS (BH * HD)          // 6144 rows per tensor (q or k)
#define ACHUNK 16               // split-K chunks for attention gram

// ---------------------------------------------------------------------------
// Device scratch
// ---------------------------------------------------------------------------
__device__ float g_qkv[3ull * BH * HD * Nn];                 // [t][b][h][d][n]
__device__ float g_inv[2 * ROWS];
__device__ float g_attn_part[(size_t)ACHUNK * BH * HD * HD];
__device__ float g_attn[(size_t)BH * HD * HD];
__device__ __nv_bfloat16 g_ctx_hi[(size_t)M1 * Cc];          // ctx [m][c] hi
__device__ __nv_bfloat16 g_ctx_lo[(size_t)M1 * Cc];          // ctx [m][c] lo
__device__ __nv_bfloat16 g_x_hi[(size_t)M1 * Cc];
__device__ __nv_bfloat16 g_x_lo[(size_t)M1 * Cc];
__device__ __nv_bfloat16 g_wq_hi[3 * Cc * Cc];
__device__ __nv_bfloat16 g_wq_lo[3 * Cc * Cc];
__device__ __nv_bfloat16 g_wp_hi[Cc * Cc];
__device__ __nv_bfloat16 g_wp_lo[Cc * Cc];

// ---------------------------------------------------------------------------
// PTX helpers (baseline target: mma.sync + ldmatrix + cp.async only)
// ---------------------------------------------------------------------------
#define LDSM4(R, A)                                                           \
    asm volatile("ldmatrix.sync.aligned.m8n8.x4.shared.b16 {%0,%1,%2,%3}, [%4];" \
        : "=r"((R)[0]), "=r"((R)[1]), "=r"((R)[2]), "=r"((R)[3]) : "r"(A))

#define MMA16816(C, A, B0, B1)                                                \
    asm volatile("mma.sync.aligned.m16n8k16.row.col.f32.bf16.bf16.f32 "       \
        "{%0,%1,%2,%3}, {%4,%5,%6,%7}, {%8,%9}, {%0,%1,%2,%3};"               \
        : "+f"((C)[0]), "+f"((C)[1]), "+f"((C)[2]), "+f"((C)[3])              \
        : "r"((A)[0]), "r"((A)[1]), "r"((A)[2]), "r"((A)[3]), "r"(B0), "r"(B1))

#define CP16(d, s)                                                            \
    asm volatile("cp.async.cg.shared.global [%0], [%1], 16;" :: "r"(d), "l"(s))
#define CPCOMMIT() asm volatile("cp.async.commit_group;" ::: "memory")
#define CPWAIT1()  asm volatile("cp.async.wait_group 1;" ::: "memory")

__device__ __forceinline__ void split2(float x, float y, uint32_t& hi, uint32_t& lo) {
    __nv_bfloat16 hx = __float2bfloat16(x), hy = __float2bfloat16(y);
    __nv_bfloat16 lx = __float2bfloat16(x - __bfloat162float(hx));
    __nv_bfloat16 ly = __float2bfloat16(y - __bfloat162float(hy));
    hi = (uint32_t)__bfloat16_as_ushort(hx) | ((uint32_t)__bfloat16_as_ushort(hy) << 16);
    lo = (uint32_t)__bfloat16_as_ushort(lx) | ((uint32_t)__bfloat16_as_ushort(ly) << 16);
}

// smem pipeline geometry: tile = 128 rows x 16 halves (32B/row, swizzled) = 4KB
// stage = 4 tiles (Ahi, Alo, Bhi, Blo) = 16KB ; 2 stages = 32KB
#define TILE_SZ  4096
#define STAGE_SZ 16384
// swizzled byte offset for (row r, 16B-chunk h in {0,1})
__device__ __forceinline__ uint32_t swz(int r, int h) {
    return (uint32_t)(r * 32 + ((h ^ ((r >> 2) & 1)) << 4));
}

// ---------------------------------------------------------------------------
// Kernel 0: fp32 -> bf16 hi/lo split (prep)
// ---------------------------------------------------------------------------
__global__ __launch_bounds__(256) void split_kernel(
    const float* __restrict__ src, __nv_bfloat16* __restrict__ hi,
    __nv_bfloat16* __restrict__ lo, int n4) {
    int i = blockIdx.x * 256 + threadIdx.x;
    if (i < n4) {
        float4 v = ((const float4*)src)[i];
        uint2 h, l;
        split2(v.x, v.y, h.x, l.x);
        split2(v.z, v.w, h.y, l.y);
        ((uint2*)hi)[i] = h;
        ((uint2*)lo)[i] = l;
    }
}

// ---------------------------------------------------------------------------
// GEMM mainloop (shared by qkv / proj): 128x128 CTA tile, K-step 16,
// cp.async 2-stage pipeline, 8 warps (4M x 2N), 3-pass hi/lo bf16 MMA.
// ---------------------------------------------------------------------------
struct GemmCtx {
    const __nv_bfloat16 *Ahi, *Alo, *Bhi, *Blo;   // row-major [*, Cc]
    size_t arow, brow;                             // starting rows
};

__device__ __forceinline__ void gemm_mainloop(
    char* sm, const GemmCtx& g, float acc[2][8][4]) {
    const int tid = threadIdx.x, l = tid & 31, w = tid >> 5;
    const int wm = w & 3, wn = w >> 2;
    const uint32_t sb = (uint32_t)__cvta_generic_to_shared(sm);

    // per-thread producer chunk: row = tid>>1, 16B half = tid&1
    const int pr = tid >> 1, ph = tid & 1;
    const uint32_t pso = swz(pr, ph);
    const size_t asrc = (g.arow + pr) * Cc + ph * 8;
    const size_t bsrc = (g.brow + pr) * Cc + ph * 8;

    // ldmatrix per-thread constants
    const int lr = l & 15;
    const uint32_t lsw = (uint32_t)((((l >> 4) ^ ((l >> 2) & 1)) & 1) << 4);
    const uint32_t aoff0 = (uint32_t)((wm * 32 + lr) * 32) + lsw;
    const uint32_t boff0 = (uint32_t)((wn * 64 + lr) * 32) + lsw;

#pragma unroll
    for (int mt = 0; mt < 2; ++mt)
#pragma unroll
        for (int ni = 0; ni < 8; ++ni)
#pragma unroll
            for (int q = 0; q < 4; ++q) acc[mt][ni][q] = 0.f;

    const int NIT = Cc / 16;    // 48
    // prologue: stages 0,1
#pragma unroll
    for (int s = 0; s < 2; ++s) {
        uint32_t db = sb + s * STAGE_SZ + pso;
        int kt = s * 16;
        CP16(db,               g.Ahi + asrc + kt);
        CP16(db + TILE_SZ,     g.Alo + asrc + kt);
        CP16(db + 2 * TILE_SZ, g.Bhi + bsrc + kt);
        CP16(db + 3 * TILE_SZ, g.Blo + bsrc + kt);
        CPCOMMIT();
    }

    for (int it = 0; it < NIT; ++it) {
        CPWAIT1();
        __syncthreads();
        const uint32_t tb = sb + (it & 1) * STAGE_SZ;

        uint32_t ah[2][4], al[2][4], bh[4][4], bl[4][4];
#pragma unroll
        for (int mt = 0; mt < 2; ++mt) {
            LDSM4(ah[mt], tb + aoff0 + mt * 512);
            LDSM4(al[mt], tb + TILE_SZ + aoff0 + mt * 512);
        }
#pragma unroll
        for (int nt = 0; nt < 4; ++nt) {
            LDSM4(bh[nt], tb + 2 * TILE_SZ + boff0 + nt * 512);
            LDSM4(bl[nt], tb + 3 * TILE_SZ + boff0 + nt * 512);
        }
#pragma unroll
        for (int mt = 0; mt < 2; ++mt)
#pragma unroll
            for (int nt = 0; nt < 4; ++nt)
#pragma unroll
                for (int h = 0; h < 2; ++h) {
                    float* c = acc[mt][nt * 2 + h];
                    MMA16816(c, ah[mt], bh[nt][h], bh[nt][h + 2]);
                    MMA16816(c, ah[mt], bl[nt][h], bl[nt][h + 2]);
                    MMA16816(c, al[mt], bh[nt][h], bh[nt][h + 2]);
                }
        __syncthreads();
        if (it + 2 < NIT) {
            uint32_t db = tb + pso;
            int kt = (it + 2) * 16;
            CP16(db,               g.Ahi + asrc + kt);
            CP16(db + TILE_SZ,     g.Alo + asrc + kt);
            CP16(db + 2 * TILE_SZ, g.Bhi + bsrc + kt);
            CP16(db + 3 * TILE_SZ, g.Blo + bsrc + kt);
        }
        CPCOMMIT();
    }
}

// ---------------------------------------------------------------------------
// Kernel 1: QKV GEMM.  Y = X @ Wqkv^T, scatter epilogue into [t][b][h][d][n].
// Grid (18 j-tiles, 256 m-tiles), 256 threads.
// ---------------------------------------------------------------------------
__global__ __launch_bounds__(256) void qkv_mma_kernel() {
    __shared__ __align__(128) char sm[34816];
    const int tid = threadIdx.x, l = tid & 31, w = tid >> 5;
    const int wm = w & 3, wn = w >> 2;
    const int j0 = blockIdx.x * 128, m0 = blockIdx.y * 128;

    GemmCtx g;
    g.Ahi = g_x_hi;  g.Alo = g_x_lo;  g.arow = (size_t)m0;
    g.Bhi = g_wq_hi; g.Blo = g_wq_lo; g.brow = (size_t)j0;

    float acc[2][8][4];
    gemm_mainloop(sm, g, acc);

    // Epilogue: stage 64 j-cols at a time as stage[j][m], coalesced scatter
    float* stage = (float*)sm;     // 64 x 132 floats = 33792B
    const int b = m0 >> 12, nb = m0 & (Nn - 1);
#pragma unroll
    for (int c = 0; c < 2; ++c) {
        __syncthreads();
        if (wn == c) {
#pragma unroll
            for (int mt = 0; mt < 2; ++mt)
#pragma unroll
                for (int ni = 0; ni < 8; ++ni) {
                    int nt = ni >> 1, h = ni & 1;
                    int jl = nt * 16 + h * 8 + (l & 3) * 2;
                    int ml = wm * 32 + mt * 16 + (l >> 2);
                    const float* d = acc[mt][ni];
                    stage[jl * 132 + ml] = d[0];
                    stage[(jl + 1) * 132 + ml] = d[1];
                    stage[jl * 132 + ml + 8] = d[2];
                    stage[(jl + 1) * 132 + ml + 8] = d[3];
                }
        }
        __syncthreads();
        {
            int jl = tid >> 2, f4 = tid & 3;
            int j = j0 + c * 64 + jl;
            int t = j / Cc, r = j - t * Cc;
            float* dst = g_qkv + ((size_t)(t * Bz + b) * Cc + r) * Nn + nb;
#pragma unroll
            for (int i = 0; i < 8; ++i) {
                int idx = f4 + i * 4;
                *(float4*)(dst + idx * 4) = *(float4*)(stage + jl * 132 + idx * 4);
            }
        }
    }
}

// ---------------------------------------------------------------------------
// Kernel 6: proj GEMM.  out = ctx @ Wp^T + bias, row-major epilogue.
// ---------------------------------------------------------------------------
__global__ __launch_bounds__(256) void proj_mma_kernel(
    const float* __restrict__ bias, float* __restrict__ out) {
    __shared__ __align__(128) char sm[34816];
    const int tid = threadIdx.x, l = tid & 31, w = tid >> 5;
    const int wm = w & 3, wn = w >> 2;
    const int j0 = blockIdx.x * 128, m0 = blockIdx.y * 128;

    GemmCtx g;
    g.Ahi = g_ctx_hi; g.Alo = g_ctx_lo; g.arow = (size_t)m0;
    g.Bhi = g_wp_hi;  g.Blo = g_wp_lo;  g.brow = (size_t)j0;

    float acc[2][8][4];
    gemm_mainloop(sm, g, acc);

    // Epilogue: stage[m][j] per 64-col chunk, coalesced row-major store + bias
    float* stage = (float*)sm;     // 128 x 68 floats = 34816B
#pragma unroll
    for (int c = 0; c < 2; ++c) {
        __syncthreads();
        if (wn == c) {
#pragma unroll
            for (int mt = 0; mt < 2; ++mt)
#pragma unroll
                for (int ni = 0; ni < 8; ++ni) {
                    int nt = ni >> 1, h = ni & 1;
                    int jl = nt * 16 + h * 8 + (l & 3) * 2;
                    int ml = wm * 32 + mt * 16 + (l >> 2);
                    const float* d = acc[mt][ni];
                    stage[ml * 68 + jl] = d[0];
                    stage[ml * 68 + jl + 1] = d[1];
                    stage[(ml + 8) * 68 + jl] = d[2];
                    stage[(ml + 8) * 68 + jl + 1] = d[3];
                }
        }
        __syncthreads();
        {
            int ml = tid >> 1, half = tid & 1;
            int jb = j0 + c * 64 + half * 32;
#pragma unroll
            for (int i = 0; i < 8; ++i) {
                float4 v = *(float4*)(stage + ml * 68 + half * 32 + i * 4);
                float4 bb = *(const float4*)(bias + jb + i * 4);
                v.x += bb.x; v.y += bb.y; v.z += bb.z; v.w += bb.w;
                *(float4*)(out + (size_t)(m0 + ml) * Cc + jb + i * 4) = v;
            }
        }
    }
}

// ---------------------------------------------------------------------------
// Kernel 2: inverse L2 norms over N for q and k rows
// ---------------------------------------------------------------------------
__global__ __launch_bounds__(256) void norms_kernel() {
    int idx = blockIdx.x;
    const float4* p4 = (const float4*)(g_qkv + (size_t)idx * Nn);
    int tid = threadIdx.x;
    float s = 0.f;
    for (int i = tid; i < Nn / 4; i += 256) {
        float4 v = p4[i];
        s = fmaf(v.x, v.x, s); s = fmaf(v.y, v.y, s);
        s = fmaf(v.z, v.z, s); s = fmaf(v.w, v.w, s);
    }
#pragma unroll
    for (int o = 16; o; o >>= 1) s += __shfl_xor_sync(0xffffffffu, s, o);
    __shared__ float red[8];
    if ((tid & 31) == 0) red[tid >> 5] = s;
    __syncthreads();
    if (tid == 0) {
        float t = 0.f;
#pragma unroll
        for (int w = 0; w < 8; ++w) t += red[w];
        g_inv[idx] = 1.0f / fmaxf(sqrtf(t), 1e-12f);
    }
}

// ---------------------------------------------------------------------------
// Kernel 3: split-K attention gram (fp32)
// ---------------------------------------------------------------------------
__global__ __launch_bounds__(256) void attn_part_kernel() {
    __shared__ float Qs[96][33];
    __shared__ float Ks[96][33];
    int bh = blockIdx.x;
    int ch = blockIdx.y;
    const int NPC = Nn / ACHUNK;
    const float* qp = g_qkv + (size_t)bh * HD * Nn + ch * NPC;
    const float* kp = g_qkv + (size_t)ROWS * Nn + (size_t)bh * HD * Nn + ch * NPC;
    int tid = threadIdx.x;
    int tx = tid & 15, ty = tid >> 4;

    float acc[6][6];
#pragma unroll
    for (int i = 0; i < 6; ++i)
#pragma unroll
        for (int j = 0; j < 6; ++j) acc[i][j] = 0.f;

    for (int n0 = 0; n0 < NPC; n0 += 32) {
        int nl = tid & 31;
        for (int r = tid >> 5; r < 96; r += 8) {
            Qs[r][nl] = qp[(size_t)r * Nn + n0 + nl];
            Ks[r][nl] = kp[(size_t)r * Nn + n0 + nl];
        }
        __syncthreads();
#pragma unroll
        for (int e = 0; e < 32; ++e) {
            float rq[6], rk[6];
#pragma unroll
            for (int i = 0; i < 6; ++i) rq[i] = Qs[i * 16 + tx][e];
#pragma unroll
            for (int j = 0; j < 6; ++j) rk[j] = Ks[j * 16 + ty][e];
#pragma unroll
            for (int i = 0; i < 6; ++i)
#pragma unroll
                for (int j = 0; j < 6; ++j)
                    acc[i][j] = fmaf(rq[i], rk[j], acc[i][j]);
        }
        __syncthreads();
    }
    float* op = g_attn_part + ((size_t)ch * BH + bh) * (HD * HD);
#pragma unroll
    for (int i = 0; i < 6; ++i)
#pragma unroll
        for (int j = 0; j < 6; ++j)
            op[(i * 16 + tx) * HD + j * 16 + ty] = acc[i][j];
}

// ---------------------------------------------------------------------------
// Kernel 4: reduce + scale + softmax
// ---------------------------------------------------------------------------
__global__ __launch_bounds__(128) void softmax_kernel(const float* __restrict__ temperature) {
    int row = blockIdx.x;
    int bh = row / HD;
    int h = bh & (Hh - 1);
    int tid = threadIdx.x;

    float v = -1e30f;
    if (tid < HD) {
        float s = 0.f;
#pragma unroll
        for (int c = 0; c < ACHUNK; ++c)
            s += g_attn_part[((size_t)c * ROWS + row) * HD + tid];
        s *= g_inv[row] * g_inv[ROWS + bh * HD + tid] * temperature[h];
        v = s;
    }
    __shared__ float red[4];
    float m = v;
#pragma unroll
    for (int o = 16; o; o >>= 1) m = fmaxf(m, __shfl_xor_sync(0xffffffffu, m, o));
    if ((tid & 31) == 0) red[tid >> 5] = m;
    __syncthreads();
    m = fmaxf(fmaxf(red[0], red[1]), fmaxf(red[2], red[3]));
    float e = (tid < HD) ? expf(v - m) : 0.f;
    __syncthreads();
    float s2 = e;
#pragma unroll
    for (int o = 16; o; o >>= 1) s2 += __shfl_xor_sync(0xffffffffu, s2, o);
    if ((tid & 31) == 0) red[tid >> 5] = s2;
    __syncthreads();
    float denom = red[0] + red[1] + red[2] + red[3];
    if (tid < HD) g_attn[(size_t)row * HD + tid] = e / denom;
}

// ---------------------------------------------------------------------------
// Kernel 5: ctx = attn @ v, emits bf16 hi/lo in [m][c] layout (proj A operand)
// ---------------------------------------------------------------------------
__global__ __launch_bounds__(256) void ctx_kernel() {
    __shared__ float At[HD * HD];      // transposed attn: At[e*96 + d]
    __shared__ float Vs[16 * 128];
    int bh = blockIdx.x, n0 = blockIdx.y * 128;
    int tid = threadIdx.x, w = tid >> 5, lane = tid & 31;
    const float* vp = g_qkv + 2ull * ROWS * Nn + (size_t)bh * HD * Nn;

    for (int i = tid; i < HD * HD; i += 256) {
        int d = i / HD, e = i % HD;
        At[e * HD + d] = g_attn[(size_t)bh * HD * HD + i];
    }

    float acc[3][16];
#pragma unroll
    for (int dg = 0; dg < 3; ++dg)
#pragma unroll
        for (int nn = 0; nn < 16; ++nn) acc[dg][nn] = 0.f;

    for (int ec = 0; ec < HD / 16; ++ec) {
        __syncthreads();
        for (int i = tid; i < 16 * 128; i += 256)
            Vs[i] = vp[(size_t)(ec * 16 + (i >> 7)) * Nn + n0 + (i & 127)];
        __syncthreads();
#pragma unroll
        for (int e = 0; e < 16; ++e) {
            float a0 = At[(ec * 16 + e) * HD + lane];
            float a1 = At[(ec * 16 + e) * HD + 32 + lane];
            float a2 = At[(ec * 16 + e) * HD + 64 + lane];
#pragma unroll
            for (int nn = 0; nn < 16; ++nn) {
                float vv = Vs[e * 128 + w * 16 + nn];
                acc[0][nn] = fmaf(a0, vv, acc[0][nn]);
                acc[1][nn] = fmaf(a1, vv, acc[1][nn]);
                acc[2][nn] = fmaf(a2, vv, acc[2][nn]);
            }
        }
    }
    int b = bh >> 3, h = bh & 7;
#pragma unroll
    for (int dg = 0; dg < 3; ++dg)
#pragma unroll
        for (int nn = 0; nn < 16; ++nn) {
            float v = acc[dg][nn];
            __nv_bfloat16 hi = __float2bfloat16(v);
            __nv_bfloat16 lo = __float2bfloat16(v - __bfloat162float(hi));
            size_t base = ((size_t)(b * Nn + n0 + w * 16 + nn)) * Cc + h * HD + dg * 32 + lane;
            g_ctx_hi[base] = hi;
            g_ctx_lo[base] = lo;
        }
}

// ---------------------------------------------------------------------------
// Launcher
// ---------------------------------------------------------------------------
extern "C" void kernel_launch(void* const* d_in, const int* in_sizes, int n_in,
                              void* d_out, int out_size) {
    const float* x      = (const float*)d_in[0];
    const float* w_qkv  = (const float*)d_in[1];
    const float* temp   = (const float*)d_in[2];
    const float* w_proj = (const float*)d_in[3];
    const float* b_proj = (const float*)d_in[4];
    float* out = (float*)d_out;

    __nv_bfloat16 *xh, *xl, *qh, *ql, *ph, *pl;
    cudaGetSymbolAddress((void**)&xh, g_x_hi);
    cudaGetSymbolAddress((void**)&xl, g_x_lo);
    cudaGetSymbolAddress((void**)&qh, g_wq_hi);
    cudaGetSymbolAddress((void**)&ql, g_wq_lo);
    cudaGetSymbolAddress((void**)&ph, g_wp_hi);
    cudaGetSymbolAddress((void**)&pl, g_wp_lo);

    const int nx = M1 * Cc / 4, nq = 3 * Cc * Cc / 4, np = Cc * Cc / 4;
    split_kernel<<<(nx + 255) / 256, 256>>>(x, xh, xl, nx);
    split_kernel<<<(nq + 255) / 256, 256>>>(w_qkv, qh, ql, nq);
    split_kernel<<<(np + 255) / 256, 256>>>(w_proj, ph, pl, np);

    qkv_mma_kernel<<<dim3(3 * Cc / 128, M1 / 128), 256>>>();
    norms_kernel<<<2 * ROWS, 256>>>();
    attn_part_kernel<<<dim3(BH, ACHUNK), 256>>>();
    softmax_kernel<<<ROWS, 128>>>(temp);
    ctx_kernel<<<dim3(BH, Nn / 128), 256>>>();
    proj_mma_kernel<<<dim3(Cc / 128, M1 / 128), 256>>>(b_proj, out);
}

// round 5
// speedup vs baseline: 1.8846x; 1.0640x over previous
#include <cuda_runtime.h>
#include <cuda_bf16.h>
#include <math.h>
#include <cstdint>

// Problem constants
#define Bz   8
#define Nn   4096
#define Cc   768
#define Hh   8
#define HD   96
#define M1   (Bz * Nn)          // 32768 tokens
#define BH   (Bz * Hh)          // 64
#define ROWS (BH * HD)          // 6144 rows per tensor (q or k)
#define ACHUNK 16               // split-K chunks for attention gram

// ---------------------------------------------------------------------------
// Device scratch
// ---------------------------------------------------------------------------
__device__ float g_qkv[3ull * BH * HD * Nn];                 // [t][b][h][d][n]
__device__ float g_inv[2 * ROWS];
__device__ float g_attn_part[(size_t)ACHUNK * BH * HD * HD];
__device__ float g_attn[(size_t)BH * HD * HD];
__device__ __nv_bfloat16 g_ctx_hi[(size_t)M1 * Cc];          // ctx [m][c] hi
__device__ __nv_bfloat16 g_ctx_lo[(size_t)M1 * Cc];          // ctx [m][c] lo
__device__ __nv_bfloat16 g_x_hi[(size_t)M1 * Cc];
__device__ __nv_bfloat16 g_x_lo[(size_t)M1 * Cc];
__device__ __nv_bfloat16 g_wq_hi[3 * Cc * Cc];
__device__ __nv_bfloat16 g_wq_lo[3 * Cc * Cc];
__device__ __nv_bfloat16 g_wp_hi[Cc * Cc];
__device__ __nv_bfloat16 g_wp_lo[Cc * Cc];

// ---------------------------------------------------------------------------
// PTX helpers (baseline target: mma.sync + ldmatrix + cp.async only)
// ---------------------------------------------------------------------------
#define LDSM4(R, A)                                                           \
    asm volatile("ldmatrix.sync.aligned.m8n8.x4.shared.b16 {%0,%1,%2,%3}, [%4];" \
        : "=r"((R)[0]), "=r"((R)[1]), "=r"((R)[2]), "=r"((R)[3]) : "r"(A))

#define MMA16816(C, A, B0, B1)                                                \
    asm volatile("mma.sync.aligned.m16n8k16.row.col.f32.bf16.bf16.f32 "       \
        "{%0,%1,%2,%3}, {%4,%5,%6,%7}, {%8,%9}, {%0,%1,%2,%3};"               \
        : "+f"((C)[0]), "+f"((C)[1]), "+f"((C)[2]), "+f"((C)[3])              \
        : "r"((A)[0]), "r"((A)[1]), "r"((A)[2]), "r"((A)[3]), "r"(B0), "r"(B1))

#define CP16(d, s)                                                            \
    asm volatile("cp.async.cg.shared.global [%0], [%1], 16;" :: "r"(d), "l"(s))
#define CPCOMMIT() asm volatile("cp.async.commit_group;" ::: "memory")
#define CPWAIT1()  asm volatile("cp.async.wait_group 1;" ::: "memory")
#define CPWAIT0()  asm volatile("cp.async.wait_group 0;" ::: "memory")

__device__ __forceinline__ void split2(float x, float y, uint32_t& hi, uint32_t& lo) {
    __nv_bfloat16 hx = __float2bfloat16(x), hy = __float2bfloat16(y);
    __nv_bfloat16 lx = __float2bfloat16(x - __bfloat162float(hx));
    __nv_bfloat16 ly = __float2bfloat16(y - __bfloat162float(hy));
    hi = (uint32_t)__bfloat16_as_ushort(hx) | ((uint32_t)__bfloat16_as_ushort(hy) << 16);
    lo = (uint32_t)__bfloat16_as_ushort(lx) | ((uint32_t)__bfloat16_as_ushort(ly) << 16);
}

// smem pipeline geometry (KC=32): tile = 128 rows x 64B (swizzled) = 8KB
// stage = 4 tiles (Ahi, Alo, Bhi, Blo) = 32KB ; 3 stages = 96KB (dynamic)
#define TILE_SZ  8192
#define STAGE_SZ 32768
#define NSTAGE   3
#define SMEM_GEMM (NSTAGE * STAGE_SZ)

// ---------------------------------------------------------------------------
// Kernel 0: fp32 -> bf16 hi/lo split (prep)
// ---------------------------------------------------------------------------
__global__ __launch_bounds__(256) void split_kernel(
    const float* __restrict__ src, __nv_bfloat16* __restrict__ hi,
    __nv_bfloat16* __restrict__ lo, int n4) {
    int i = blockIdx.x * 256 + threadIdx.x;
    if (i < n4) {
        float4 v = ((const float4*)src)[i];
        uint2 h, l;
        split2(v.x, v.y, h.x, l.x);
        split2(v.z, v.w, h.y, l.y);
        ((uint2*)hi)[i] = h;
        ((uint2*)lo)[i] = l;
    }
}

// ---------------------------------------------------------------------------
// GEMM mainloop: 128x128 CTA tile, K-step 32, 3-stage cp.async pipeline,
// ONE __syncthreads per iteration. 8 warps (4M x 2N), 3-pass hi/lo bf16 MMA.
// Swizzle: smem offset(r, chunk) = r*64 + ((chunk ^ ((r>>1)&3)) << 4)
// ---------------------------------------------------------------------------
struct GemmCtx {
    const __nv_bfloat16 *Ahi, *Alo, *Bhi, *Blo;   // row-major [*, Cc]
    size_t arow, brow;                             // starting rows
};

__device__ __forceinline__ void gemm_mainloop(
    char* sm, const GemmCtx& g, float acc[2][8][4]) {
    const int tid = threadIdx.x, l = tid & 31, w = tid >> 5;
    const int wm = w & 3, wn = w >> 2;
    const uint32_t sb = (uint32_t)__cvta_generic_to_shared(sm);

    // producer: row = tid>>1 (0..127), chunks c0 = (tid&1)*2 and c0+1
    const int pr = tid >> 1, pc0 = (tid & 1) * 2;
    const int prx = (pr >> 1) & 3;
    const uint32_t po0 = (uint32_t)(pr * 64 + ((pc0 ^ prx) << 4));
    const uint32_t po1 = (uint32_t)(pr * 64 + (((pc0 + 1) ^ prx) << 4));
    const size_t asrc = (g.arow + pr) * Cc + pc0 * 8;
    const size_t bsrc = (g.brow + pr) * Cc + pc0 * 8;

    // ldmatrix per-thread constants
    const int lr = l & 15, hsel = l >> 4;
    const int rowA = wm * 32 + lr, rowB = wn * 64 + lr;
    const int rxa = (rowA >> 1) & 3, rxb = (rowB >> 1) & 3;
    // swizzle term per k16 block kk: ((2*kk + hsel) ^ rx) << 4   (rx invariant
    // under +16/+32 row shifts since 16/2 = 8 ≡ 0 mod 4)
    const uint32_t aswz[2] = { (uint32_t)(((hsel ^ rxa) << 4)),
                               (uint32_t)((((2 + hsel) ^ rxa) << 4)) };
    const uint32_t bswz[2] = { (uint32_t)(((hsel ^ rxb) << 4)),
                               (uint32_t)((((2 + hsel) ^ rxb) << 4)) };
    const uint32_t abase = (uint32_t)(rowA * 64);
    const uint32_t bbase = (uint32_t)(rowB * 64);

#pragma unroll
    for (int mt = 0; mt < 2; ++mt)
#pragma unroll
        for (int ni = 0; ni < 8; ++ni)
#pragma unroll
            for (int q = 0; q < 4; ++q) acc[mt][ni][q] = 0.f;

    const int NIT = Cc / 32;    // 24

    // prologue: fill stages 0,1
#pragma unroll
    for (int s = 0; s < 2; ++s) {
        uint32_t db = sb + s * STAGE_SZ;
        int kt = s * 32;
        CP16(db + po0,               g.Ahi + asrc + kt);
        CP16(db + po1,               g.Ahi + asrc + kt + 8);
        CP16(db + TILE_SZ + po0,     g.Alo + asrc + kt);
        CP16(db + TILE_SZ + po1,     g.Alo + asrc + kt + 8);
        CP16(db + 2 * TILE_SZ + po0, g.Bhi + bsrc + kt);
        CP16(db + 2 * TILE_SZ + po1, g.Bhi + bsrc + kt + 8);
        CP16(db + 3 * TILE_SZ + po0, g.Blo + bsrc + kt);
        CP16(db + 3 * TILE_SZ + po1, g.Blo + bsrc + kt + 8);
        CPCOMMIT();
    }

    int buf = 0, fbuf = 2;
    for (int it = 0; it < NIT; ++it) {
        CPWAIT1();            // stage `it` landed
        __syncthreads();      // all warps done reading stage it-1 (buffer fbuf)

        if (it + 2 < NIT) {   // fill 2 ahead into the just-freed buffer
            uint32_t db = sb + fbuf * STAGE_SZ;
            int kt = (it + 2) * 32;
            CP16(db + po0,               g.Ahi + asrc + kt);
            CP16(db + po1,               g.Ahi + asrc + kt + 8);
            CP16(db + TILE_SZ + po0,     g.Alo + asrc + kt);
            CP16(db + TILE_SZ + po1,     g.Alo + asrc + kt + 8);
            CP16(db + 2 * TILE_SZ + po0, g.Bhi + bsrc + kt);
            CP16(db + 2 * TILE_SZ + po1, g.Bhi + bsrc + kt + 8);
            CP16(db + 3 * TILE_SZ + po0, g.Blo + bsrc + kt);
            CP16(db + 3 * TILE_SZ + po1, g.Blo + bsrc + kt + 8);
        }
        CPCOMMIT();

        const uint32_t tb = sb + buf * STAGE_SZ;
#pragma unroll
        for (int kk = 0; kk < 2; ++kk) {
            uint32_t ah[2][4], al[2][4], bh[4][4], bl[4][4];
#pragma unroll
            for (int mt = 0; mt < 2; ++mt) {
                uint32_t o = abase + mt * 1024 + aswz[kk];
                LDSM4(ah[mt], tb + o);
                LDSM4(al[mt], tb + TILE_SZ + o);
            }
#pragma unroll
            for (int nt = 0; nt < 4; ++nt) {
                uint32_t o = bbase + nt * 1024 + bswz[kk];
                LDSM4(bh[nt], tb + 2 * TILE_SZ + o);
                LDSM4(bl[nt], tb + 3 * TILE_SZ + o);
            }
#pragma unroll
            for (int mt = 0; mt < 2; ++mt)
#pragma unroll
                for (int nt = 0; nt < 4; ++nt)
#pragma unroll
                    for (int h = 0; h < 2; ++h) {
                        float* c = acc[mt][nt * 2 + h];
                        MMA16816(c, ah[mt], bh[nt][h], bh[nt][h + 2]);
                        MMA16816(c, ah[mt], bl[nt][h], bl[nt][h + 2]);
                        MMA16816(c, al[mt], bh[nt][h], bh[nt][h + 2]);
                    }
        }
        buf = (buf == 2) ? 0 : buf + 1;
        fbuf = (fbuf == 2) ? 0 : fbuf + 1;
    }
    CPWAIT0();
}

// ---------------------------------------------------------------------------
// Kernel 1: QKV GEMM.  Y = X @ Wqkv^T, scatter epilogue into [t][b][h][d][n].
// ---------------------------------------------------------------------------
__global__ __launch_bounds__(256) void qkv_mma_kernel() {
    extern __shared__ __align__(128) char sm[];
    const int tid = threadIdx.x, l = tid & 31, w = tid >> 5;
    const int wm = w & 3, wn = w >> 2;
    const int j0 = blockIdx.x * 128, m0 = blockIdx.y * 128;

    GemmCtx g;
    g.Ahi = g_x_hi;  g.Alo = g_x_lo;  g.arow = (size_t)m0;
    g.Bhi = g_wq_hi; g.Blo = g_wq_lo; g.brow = (size_t)j0;

    float acc[2][8][4];
    gemm_mainloop(sm, g, acc);

    // Epilogue: stage 64 j-cols at a time as stage[j][m], coalesced scatter
    float* stage = (float*)sm;     // 64 x 132 floats = 33792B
    const int b = m0 >> 12, nb = m0 & (Nn - 1);
#pragma unroll
    for (int c = 0; c < 2; ++c) {
        __syncthreads();
        if (wn == c) {
#pragma unroll
            for (int mt = 0; mt < 2; ++mt)
#pragma unroll
                for (int ni = 0; ni < 8; ++ni) {
                    int nt = ni >> 1, h = ni & 1;
                    int jl = nt * 16 + h * 8 + (l & 3) * 2;
                    int ml = wm * 32 + mt * 16 + (l >> 2);
                    const float* d = acc[mt][ni];
                    stage[jl * 132 + ml] = d[0];
                    stage[(jl + 1) * 132 + ml] = d[1];
                    stage[jl * 132 + ml + 8] = d[2];
                    stage[(jl + 1) * 132 + ml + 8] = d[3];
                }
        }
        __syncthreads();
        {
            int jl = tid >> 2, f4 = tid & 3;
            int j = j0 + c * 64 + jl;
            int t = j / Cc, r = j - t * Cc;
            float* dst = g_qkv + ((size_t)(t * Bz + b) * Cc + r) * Nn + nb;
#pragma unroll
            for (int i = 0; i < 8; ++i) {
                int idx = f4 + i * 4;
                *(float4*)(dst + idx * 4) = *(float4*)(stage + jl * 132 + idx * 4);
            }
        }
    }
}

// ---------------------------------------------------------------------------
// Kernel 6: proj GEMM.  out = ctx @ Wp^T + bias, row-major epilogue.
// ---------------------------------------------------------------------------
__global__ __launch_bounds__(256) void proj_mma_kernel(
    const float* __restrict__ bias, float* __restrict__ out) {
    extern __shared__ __align__(128) char sm[];
    const int tid = threadIdx.x, l = tid & 31, w = tid >> 5;
    const int wm = w & 3, wn = w >> 2;
    const int j0 = blockIdx.x * 128, m0 = blockIdx.y * 128;

    GemmCtx g;
    g.Ahi = g_ctx_hi; g.Alo = g_ctx_lo; g.arow = (size_t)m0;
    g.Bhi = g_wp_hi;  g.Blo = g_wp_lo;  g.brow = (size_t)j0;

    float acc[2][8][4];
    gemm_mainloop(sm, g, acc);

    // Epilogue: stage[m][j] per 64-col chunk, coalesced row-major store + bias
    float* stage = (float*)sm;     // 128 x 68 floats = 34816B
#pragma unroll
    for (int c = 0; c < 2; ++c) {
        __syncthreads();
        if (wn == c) {
#pragma unroll
            for (int mt = 0; mt < 2; ++mt)
#pragma unroll
                for (int ni = 0; ni < 8; ++ni) {
                    int nt = ni >> 1, h = ni & 1;
                    int jl = nt * 16 + h * 8 + (l & 3) * 2;
                    int ml = wm * 32 + mt * 16 + (l >> 2);
                    const float* d = acc[mt][ni];
                    stage[ml * 68 + jl] = d[0];
                    stage[ml * 68 + jl + 1] = d[1];
                    stage[(ml + 8) * 68 + jl] = d[2];
                    stage[(ml + 8) * 68 + jl + 1] = d[3];
                }
        }
        __syncthreads();
        {
            int ml = tid >> 1, half = tid & 1;
            int jb = j0 + c * 64 + half * 32;
#pragma unroll
            for (int i = 0; i < 8; ++i) {
                float4 v = *(float4*)(stage + ml * 68 + half * 32 + i * 4);
                float4 bb = *(const float4*)(bias + jb + i * 4);
                v.x += bb.x; v.y += bb.y; v.z += bb.z; v.w += bb.w;
                *(float4*)(out + (size_t)(m0 + ml) * Cc + jb + i * 4) = v;
            }
        }
    }
}

// ---------------------------------------------------------------------------
// Kernel 2: inverse L2 norms over N for q and k rows
// ---------------------------------------------------------------------------
__global__ __launch_bounds__(256) void norms_kernel() {
    int idx = blockIdx.x;
    const float4* p4 = (const float4*)(g_qkv + (size_t)idx * Nn);
    int tid = threadIdx.x;
    float s = 0.f;
    for (int i = tid; i < Nn / 4; i += 256) {
        float4 v = p4[i];
        s = fmaf(v.x, v.x, s); s = fmaf(v.y, v.y, s);
        s = fmaf(v.z, v.z, s); s = fmaf(v.w, v.w, s);
    }
#pragma unroll
    for (int o = 16; o; o >>= 1) s += __shfl_xor_sync(0xffffffffu, s, o);
    __shared__ float red[8];
    if ((tid & 31) == 0) red[tid >> 5] = s;
    __syncthreads();
    if (tid == 0) {
        float t = 0.f;
#pragma unroll
        for (int w = 0; w < 8; ++w) t += red[w];
        g_inv[idx] = 1.0f / fmaxf(sqrtf(t), 1e-12f);
    }
}

// ---------------------------------------------------------------------------
// Kernel 3: split-K attention gram (fp32)
// ---------------------------------------------------------------------------
__global__ __launch_bounds__(256) void attn_part_kernel() {
    __shared__ float Qs[96][33];
    __shared__ float Ks[96][33];
    int bh = blockIdx.x;
    int ch = blockIdx.y;
    const int NPC = Nn / ACHUNK;
    const float* qp = g_qkv + (size_t)bh * HD * Nn + ch * NPC;
    const float* kp = g_qkv + (size_t)ROWS * Nn + (size_t)bh * HD * Nn + ch * NPC;
    int tid = threadIdx.x;
    int tx = tid & 15, ty = tid >> 4;

    float acc[6][6];
#pragma unroll
    for (int i = 0; i < 6; ++i)
#pragma unroll
        for (int j = 0; j < 6; ++j) acc[i][j] = 0.f;

    for (int n0 = 0; n0 < NPC; n0 += 32) {
        int nl = tid & 31;
        for (int r = tid >> 5; r < 96; r += 8) {
            Qs[r][nl] = qp[(size_t)r * Nn + n0 + nl];
            Ks[r][nl] = kp[(size_t)r * Nn + n0 + nl];
        }
        __syncthreads();
#pragma unroll
        for (int e = 0; e < 32; ++e) {
            float rq[6], rk[6];
#pragma unroll
            for (int i = 0; i < 6; ++i) rq[i] = Qs[i * 16 + tx][e];
#pragma unroll
            for (int j = 0; j < 6; ++j) rk[j] = Ks[j * 16 + ty][e];
#pragma unroll
            for (int i = 0; i < 6; ++i)
#pragma unroll
                for (int j = 0; j < 6; ++j)
                    acc[i][j] = fmaf(rq[i], rk[j], acc[i][j]);
        }
        __syncthreads();
    }
    float* op = g_attn_part + ((size_t)ch * BH + bh) * (HD * HD);
#pragma unroll
    for (int i = 0; i < 6; ++i)
#pragma unroll
        for (int j = 0; j < 6; ++j)
            op[(i * 16 + tx) * HD + j * 16 + ty] = acc[i][j];
}

// ---------------------------------------------------------------------------
// Kernel 4: reduce + scale + softmax
// ---------------------------------------------------------------------------
__global__ __launch_bounds__(128) void softmax_kernel(const float* __restrict__ temperature) {
    int row = blockIdx.x;
    int bh = row / HD;
    int h = bh & (Hh - 1);
    int tid = threadIdx.x;

    float v = -1e30f;
    if (tid < HD) {
        float s = 0.f;
#pragma unroll
        for (int c = 0; c < ACHUNK; ++c)
            s += g_attn_part[((size_t)c * ROWS + row) * HD + tid];
        s *= g_inv[row] * g_inv[ROWS + bh * HD + tid] * temperature[h];
        v = s;
    }
    __shared__ float red[4];
    float m = v;
#pragma unroll
    for (int o = 16; o; o >>= 1) m = fmaxf(m, __shfl_xor_sync(0xffffffffu, m, o));
    if ((tid & 31) == 0) red[tid >> 5] = m;
    __syncthreads();
    m = fmaxf(fmaxf(red[0], red[1]), fmaxf(red[2], red[3]));
    float e = (tid < HD) ? expf(v - m) : 0.f;
    __syncthreads();
    float s2 = e;
#pragma unroll
    for (int o = 16; o; o >>= 1) s2 += __shfl_xor_sync(0xffffffffu, s2, o);
    if ((tid & 31) == 0) red[tid >> 5] = s2;
    __syncthreads();
    float denom = red[0] + red[1] + red[2] + red[3];
    if (tid < HD) g_attn[(size_t)row * HD + tid] = e / denom;
}

// ---------------------------------------------------------------------------
// Kernel 5: ctx = attn @ v, emits bf16 hi/lo in [m][c] layout (proj A operand)
// ---------------------------------------------------------------------------
__global__ __launch_bounds__(256) void ctx_kernel() {
    __shared__ float At[HD * HD];      // transposed attn: At[e*96 + d]
    __shared__ float Vs[16 * 128];
    int bh = blockIdx.x, n0 = blockIdx.y * 128;
    int tid = threadIdx.x, w = tid >> 5, lane = tid & 31;
    const float* vp = g_qkv + 2ull * ROWS * Nn + (size_t)bh * HD * Nn;

    for (int i = tid; i < HD * HD; i += 256) {
        int d = i / HD, e = i % HD;
        At[e * HD + d] = g_attn[(size_t)bh * HD * HD + i];
    }

    float acc[3][16];
#pragma unroll
    for (int dg = 0; dg < 3; ++dg)
#pragma unroll
        for (int nn = 0; nn < 16; ++nn) acc[dg][nn] = 0.f;

    for (int ec = 0; ec < HD / 16; ++ec) {
        __syncthreads();
        for (int i = tid; i < 16 * 128; i += 256)
            Vs[i] = vp[(size_t)(ec * 16 + (i >> 7)) * Nn + n0 + (i & 127)];
        __syncthreads();
#pragma unroll
        for (int e = 0; e < 16; ++e) {
            float a0 = At[(ec * 16 + e) * HD + lane];
            float a1 = At[(ec * 16 + e) * HD + 32 + lane];
            float a2 = At[(ec * 16 + e) * HD + 64 + lane];
#pragma unroll
            for (int nn = 0; nn < 16; ++nn) {
                float vv = Vs[e * 128 + w * 16 + nn];
                acc[0][nn] = fmaf(a0, vv, acc[0][nn]);
                acc[1][nn] = fmaf(a1, vv, acc[1][nn]);
                acc[2][nn] = fmaf(a2, vv, acc[2][nn]);
            }
        }
    }
    int b = bh >> 3, h = bh & 7;
#pragma unroll
    for (int dg = 0; dg < 3; ++dg)
#pragma unroll
        for (int nn = 0; nn < 16; ++nn) {
            float v = acc[dg][nn];
            __nv_bfloat16 hi = __float2bfloat16(v);
            __nv_bfloat16 lo = __float2bfloat16(v - __bfloat162float(hi));
            size_t base = ((size_t)(b * Nn + n0 + w * 16 + nn)) * Cc + h * HD + dg * 32 + lane;
            g_ctx_hi[base] = hi;
            g_ctx_lo[base] = lo;
        }
}

// ---------------------------------------------------------------------------
// Launcher
// ---------------------------------------------------------------------------
extern "C" void kernel_launch(void* const* d_in, const int* in_sizes, int n_in,
                              void* d_out, int out_size) {
    const float* x      = (const float*)d_in[0];
    const float* w_qkv  = (const float*)d_in[1];
    const float* temp   = (const float*)d_in[2];
    const float* w_proj = (const float*)d_in[3];
    const float* b_proj = (const float*)d_in[4];
    float* out = (float*)d_out;

    __nv_bfloat16 *xh, *xl, *qh, *ql, *ph, *pl;
    cudaGetSymbolAddress((void**)&xh, g_x_hi);
    cudaGetSymbolAddress((void**)&xl, g_x_lo);
    cudaGetSymbolAddress((void**)&qh, g_wq_hi);
    cudaGetSymbolAddress((void**)&ql, g_wq_lo);
    cudaGetSymbolAddress((void**)&ph, g_wp_hi);
    cudaGetSymbolAddress((void**)&pl, g_wp_lo);

    cudaFuncSetAttribute(qkv_mma_kernel,
                         cudaFuncAttributeMaxDynamicSharedMemorySize, SMEM_GEMM);
    cudaFuncSetAttribute(proj_mma_kernel,
                         cudaFuncAttributeMaxDynamicSharedMemorySize, SMEM_GEMM);

    const int nx = M1 * Cc / 4, nq = 3 * Cc * Cc / 4, np = Cc * Cc / 4;
    split_kernel<<<(nx + 255) / 256, 256>>>(x, xh, xl, nx);
    split_kernel<<<(nq + 255) / 256, 256>>>(w_qkv, qh, ql, nq);
    split_kernel<<<(np + 255) / 256, 256>>>(w_proj, ph, pl, np);

    qkv_mma_kernel<<<dim3(3 * Cc / 128, M1 / 128), 256, SMEM_GEMM>>>();
    norms_kernel<<<2 * ROWS, 256>>>();
    attn_part_kernel<<<dim3(BH, ACHUNK), 256>>>();
    softmax_kernel<<<ROWS, 128>>>(temp);
    ctx_kernel<<<dim3(BH, Nn / 128), 256>>>();
    proj_mma_kernel<<<dim3(Cc / 128, M1 / 128), 256, SMEM_GEMM>>>(b_proj, out);
}